// round 4
// baseline (speedup 1.0000x reference)
#include <cuda_runtime.h>
#include <cuda_fp16.h>
#include <stdint.h>

// Problem constants
#define NS   36      // streams
#define HH   256     // hidden
#define GWW  1024    // gate width
#define BB   32      // batch
#define TST  128     // timesteps
#define FEAT 9472    // (NS+1)*HH

// ---------------- device scratch (static; no allocation) ----------------
// Weights in mma-fragment order, hi/lo fp16 pairs.
// Per (matmul m, stream n): 2048 fragments * 32 lanes * 8 halves = 524288 halves.
__device__ __half g_B[3u * NS * 524288u];              // 113 MB
// h buffers in A-fragment order, hi/lo: per stream 16ks*2rt*32lane*16halves = 16384 halves.
__device__ __half g_H1[2][NS][16384];
__device__ __half g_H2[2][NS][16384];
__device__ float  g_c1[NS * HH * BB];
__device__ float  g_c2[NS * HH * BB];
__device__ float  g_Wih1p[NS * GWW];                   // permuted gate order (u*4+gt)
__device__ float  g_bg1p[NS * GWW];
__device__ float  g_bg2p[NS * GWW];
__device__ float  g_featT[FEAT * BB];                  // featT[k][b]
__device__ float  g_act[BB * HH];                      // fc1 output (post-ReLU)

// ---------------- mma wrapper ----------------
__device__ __forceinline__ void mma16816(float c[4],
                                         uint32_t a0, uint32_t a1, uint32_t a2, uint32_t a3,
                                         uint32_t b0, uint32_t b1) {
    asm volatile(
        "mma.sync.aligned.m16n8k16.row.col.f32.f16.f16.f32 "
        "{%0,%1,%2,%3}, {%4,%5,%6,%7}, {%8,%9}, {%0,%1,%2,%3};"
        : "+f"(c[0]), "+f"(c[1]), "+f"(c[2]), "+f"(c[3])
        : "r"(a0), "r"(a1), "r"(a2), "r"(a3), "r"(b0), "r"(b1));
}

// ---------------- setup kernels ----------------
// Convert big weights (Whh1, Wih2, Whh2) fp32 -> fragment-ordered hi/lo fp16.
// One thread per (m, n, frag, lane); writes 8 halves (4 hi + 4 lo).
__global__ void conv_big(const float* __restrict__ Whh1,
                         const float* __restrict__ Wih2,
                         const float* __restrict__ Whh2) {
    int idx = blockIdx.x * 256 + threadIdx.x;        // 3*36*2048*32 = 7,077,888
    if (idx >= 3 * NS * 2048 * 32) return;
    int lane = idx & 31;
    int r    = idx >> 5;
    int frag = r & 2047;          // ((bl*4+w)*8 + ct)*16 + ks
    int r2   = r >> 11;
    int n    = r2 % NS;
    int m    = r2 / NS;
    int ks   = frag & 15;
    int ct   = (frag >> 4) & 7;
    int blw  = frag >> 7;         // bl*4 + w in [0,16)
    int col  = blw * 64 + ct * 8 + (lane >> 2);   // global gate-col (permuted) [0,1024)
    int i4   = lane & 3;
    int u    = col >> 2;
    int gt   = col & 3;
    int g_orig = gt * 256 + u;    // original torch gate index
    const float* W = (m == 0) ? Whh1 : ((m == 1) ? Wih2 : Whh2);
    const float* src = W + ((size_t)n * GWW + g_orig) * HH + ks * 16;
    __half* dst = g_B + ((size_t)(m * NS + n) * 2048 + frag) * 256 + lane * 8;
    int kk0 = 2 * i4;
    int kks[4] = {kk0, kk0 + 1, kk0 + 8, kk0 + 9};
#pragma unroll
    for (int j = 0; j < 4; j++) {
        float v = src[kks[j]];
        __half hi = __float2half_rn(v);
        __half lo = __float2half_rn(v - __half2float(hi));
        dst[j]     = hi;
        dst[4 + j] = lo;
    }
}

// Permute Wih1 and fused biases into u*4+gt order.
__global__ void conv_small(const float* __restrict__ Wih1,
                           const float* __restrict__ bih1, const float* __restrict__ bhh1,
                           const float* __restrict__ bih2, const float* __restrict__ bhh2) {
    int idx = blockIdx.x * 256 + threadIdx.x;        // 36*1024
    if (idx >= NS * GWW) return;
    int n = idx >> 10;
    int col = idx & 1023;
    int u = col >> 2, gt = col & 3;
    int go = gt * 256 + u;
    int s = n * GWW + go;
    g_Wih1p[idx] = Wih1[s];
    g_bg1p[idx]  = bih1[s] + bhh1[s];
    g_bg2p[idx]  = bih2[s] + bhh2[s];
}

__global__ void init_kernel() {
    int idx = blockIdx.x * 256 + threadIdx.x;
    if (idx < 2 * NS * 16384 / 2) {                  // 589824 u32: both parities
        ((uint32_t*)g_H1)[idx] = 0u;
        ((uint32_t*)g_H2)[idx] = 0u;
    }
    if (idx < NS * HH * BB) {                        // 294912 floats
        g_c1[idx] = 0.f;
        g_c2[idx] = 0.f;
    }
}

__global__ void spec_kernel(const float* __restrict__ spec,
                            const float* __restrict__ Wspec,
                            const float* __restrict__ bspec) {
    int j = threadIdx.x;                             // [0,256)
    for (int b = 0; b < BB; b++) {
        float s = bspec[j];
#pragma unroll
        for (int i = 0; i < 6; i++) s += spec[b * 6 + i] * Wspec[i * HH + j];
        g_featT[(NS * HH + j) * BB + b] = s;
    }
}

// ---------------- GEMM core: acc += 3-term hi/lo mma over [32 x 256] x [256 x 256cols] ----------------
__device__ __forceinline__ void gemm3(float acc[2][8][4], const uint4* __restrict__ A,
                                      const uint4* __restrict__ Bw, int lane) {
#pragma unroll 2
    for (int ks = 0; ks < 16; ks++) {
        uint4 ahi[2], alo[2];
#pragma unroll
        for (int rt = 0; rt < 2; rt++) {
            const uint4* ap = A + ((ks * 2 + rt) * 32 + lane) * 2;
            ahi[rt] = ap[0];
            alo[rt] = ap[1];
        }
#pragma unroll
        for (int ct = 0; ct < 8; ct++) {
            uint4 b = Bw[(ct * 16 + ks) * 32 + lane];
#pragma unroll
            for (int rt = 0; rt < 2; rt++) {
                mma16816(acc[rt][ct], ahi[rt].x, ahi[rt].y, ahi[rt].z, ahi[rt].w, b.x, b.y);  // Hhi*Whi
                mma16816(acc[rt][ct], ahi[rt].x, ahi[rt].y, ahi[rt].z, ahi[rt].w, b.z, b.w);  // Hhi*Wlo
                mma16816(acc[rt][ct], alo[rt].x, alo[rt].y, alo[rt].z, alo[rt].w, b.x, b.y);  // Hlo*Whi
            }
        }
    }
}

__device__ __forceinline__ float sigf(float v) { return 1.0f / (1.0f + expf(-v)); }

// ---------------- per-step kernel: blocks [0,144) = layer1(t), [144,288) = layer2(t-1) ----------------
__global__ void __launch_bounds__(128) step_kernel(int t, const float* __restrict__ x) {
    int bid = blockIdx.x;
    bool isL2 = (bid >= 144);
    int lb = isL2 ? bid - 144 : bid;
    int st = isL2 ? t - 1 : t;
    if (st < 0 || st > TST - 1) return;
    int n = lb >> 2, bl = lb & 3;
    int tid = threadIdx.x, w = tid >> 5, lane = tid & 31;
    int rp = st & 1, wp = rp ^ 1;

    __shared__ float sg[BB * 256];

    float acc[2][8][4];
#pragma unroll
    for (int a = 0; a < 2; a++)
#pragma unroll
        for (int b = 0; b < 8; b++)
#pragma unroll
            for (int c = 0; c < 4; c++) acc[a][b][c] = 0.f;

    const uint4* Bu4 = (const uint4*)g_B;
    size_t wfrag = (size_t)(bl * 4 + w) * 128;   // warp's base fragment index within (m,n)

    if (!isL2) {
        const uint4* Bw = Bu4 + ((size_t)(0 * NS + n) * 2048 + wfrag) * 32;
        gemm3(acc, (const uint4*)g_H1[rp][n], Bw, lane);
    } else {
        // h1(st) lives at parity (st+1)&1 == wp
        const uint4* Bw1 = Bu4 + ((size_t)(1 * NS + n) * 2048 + wfrag) * 32;
        gemm3(acc, (const uint4*)g_H1[wp][n], Bw1, lane);
        const uint4* Bw2 = Bu4 + ((size_t)(2 * NS + n) * 2048 + wfrag) * 32;
        gemm3(acc, (const uint4*)g_H2[rp][n], Bw2, lane);
    }

    // dump accumulators to shared: rows = batch, cols = block-local gate col (u_local*4+gt)
    int g8 = lane >> 2;
    int i2 = (lane & 3) * 2;
#pragma unroll
    for (int rt = 0; rt < 2; rt++)
#pragma unroll
        for (int ct = 0; ct < 8; ct++) {
            int col = w * 64 + ct * 8 + i2;
            int r0 = rt * 16 + g8;
            sg[r0 * 256 + col]           = acc[rt][ct][0];
            sg[r0 * 256 + col + 1]       = acc[rt][ct][1];
            sg[(r0 + 8) * 256 + col]     = acc[rt][ct][2];
            sg[(r0 + 8) * 256 + col + 1] = acc[rt][ct][3];
        }
    __syncthreads();

    float* cbuf = isL2 ? g_c2 : g_c1;
    const float* bias = isL2 ? g_bg2p : g_bg1p;
    __half* Hout = isL2 ? g_H2[wp][n] : g_H1[wp][n];

    for (int e = tid; e < BB * 64; e += 128) {
        int b  = e & 31;
        int ul = e >> 5;                 // local unit [0,64)
        int u  = bl * 64 + ul;           // unit [0,256)
        int cb = ul * 4;
        int colg = bl * 256 + cb;        // permuted col within stream
        float ip = sg[b * 256 + cb + 0] + bias[n * GWW + colg + 0];
        float fp = sg[b * 256 + cb + 1] + bias[n * GWW + colg + 1];
        float gp = sg[b * 256 + cb + 2] + bias[n * GWW + colg + 2];
        float op = sg[b * 256 + cb + 3] + bias[n * GWW + colg + 3];
        if (!isL2) {
            float xv = x[(b * TST + st) * NS + n];
            ip += xv * g_Wih1p[n * GWW + colg + 0];
            fp += xv * g_Wih1p[n * GWW + colg + 1];
            gp += xv * g_Wih1p[n * GWW + colg + 2];
            op += xv * g_Wih1p[n * GWW + colg + 3];
        }
        float iv = sigf(ip), fv = sigf(fp), gv = tanhf(gp), ov = sigf(op);
        int ci = (n * HH + u) * BB + b;
        float cv = fv * cbuf[ci] + iv * gv;
        cbuf[ci] = cv;
        float hv = ov * tanhf(cv);

        // write h into A-fragment layout (hi + lo)
        int ks = u >> 4, kk = u & 15;
        int rt = b >> 4, rl = b & 15;
        int gg = rl & 7, hirow = rl >> 3;
        int ii = (kk & 7) >> 1, p = kk & 1, hik = kk >> 3;
        int lane2 = gg * 4 + ii;
        int j = hik * 4 + hirow * 2 + p;
        __half hi = __float2half_rn(hv);
        __half lo = __float2half_rn(hv - __half2float(hi));
        __half* hp = Hout + ((ks * 2 + rt) * 32 + lane2) * 16;
        hp[j]     = hi;
        hp[j + 8] = lo;

        if (isL2) g_featT[(n * HH + u) * BB + b] = hv;
    }
}

// ---------------- classifier ----------------
__global__ void fc1_kernel(const float* __restrict__ Wp1, const float* __restrict__ bp1) {
    int tid = threadIdx.x;
    int b = tid & 31;
    int tj = tid >> 5;                      // [0,8)
    int j = blockIdx.x * 8 + tj;            // [0,256)
    const float* ft = g_featT + b;
    const float* wc = Wp1 + j;
    float a0 = 0.f, a1 = 0.f, a2 = 0.f, a3 = 0.f;
#pragma unroll 4
    for (int k = 0; k < FEAT; k += 4) {
        a0 += ft[(k + 0) * BB] * wc[(size_t)(k + 0) * HH];
        a1 += ft[(k + 1) * BB] * wc[(size_t)(k + 1) * HH];
        a2 += ft[(k + 2) * BB] * wc[(size_t)(k + 2) * HH];
        a3 += ft[(k + 3) * BB] * wc[(size_t)(k + 3) * HH];
    }
    float acc = bp1[j] + ((a0 + a1) + (a2 + a3));
    g_act[b * HH + j] = fmaxf(acc, 0.f);
}

__global__ void fc2_kernel(const float* __restrict__ Wp2, const float* __restrict__ bp2,
                           float* __restrict__ out) {
    int tid = threadIdx.x;
    if (tid >= BB * 30) return;
    int b = tid / 30, o = tid % 30;
    float acc = bp2[o];
#pragma unroll 8
    for (int k = 0; k < HH; k++) acc += g_act[b * HH + k] * Wp2[k * 30 + o];
    out[b * 30 + o] = acc;
}

// ---------------- launch ----------------
extern "C" void kernel_launch(void* const* d_in, const int* in_sizes, int n_in,
                              void* d_out, int out_size) {
    const float* x     = (const float*)d_in[0];
    const float* spec  = (const float*)d_in[1];
    const float* Wih1  = (const float*)d_in[2];
    const float* Whh1  = (const float*)d_in[3];
    const float* bih1  = (const float*)d_in[4];
    const float* bhh1  = (const float*)d_in[5];
    const float* Wih2  = (const float*)d_in[6];
    const float* Whh2  = (const float*)d_in[7];
    const float* bih2  = (const float*)d_in[8];
    const float* bhh2  = (const float*)d_in[9];
    const float* Wspec = (const float*)d_in[10];
    const float* bspec = (const float*)d_in[11];
    const float* Wp1   = (const float*)d_in[12];
    const float* bp1   = (const float*)d_in[13];
    const float* Wp2   = (const float*)d_in[14];
    const float* bp2   = (const float*)d_in[15];
    float* out = (float*)d_out;

    conv_big<<<27648, 256>>>(Whh1, Wih2, Whh2);
    conv_small<<<144, 256>>>(Wih1, bih1, bhh1, bih2, bhh2);
    init_kernel<<<2304, 256>>>();
    spec_kernel<<<1, 256>>>(spec, Wspec, bspec);

    for (int t = 0; t <= TST; t++)
        step_kernel<<<288, 128>>>(t, x);

    fc1_kernel<<<32, 256>>>(Wp1, bp1);
    fc2_kernel<<<1, 960>>>(Wp2, bp2, out);
}

// round 6
// speedup vs baseline: 1.3247x; 1.3247x over previous
#include <cuda_runtime.h>
#include <cuda_fp16.h>
#include <stdint.h>

// Problem constants
#define NS   36      // streams
#define HH   256     // hidden
#define GWW  1024    // gate width
#define BB   32      // batch
#define TST  128     // timesteps
#define FEAT 9472    // (NS+1)*HH

// ---------------- device scratch (static; no allocation) ----------------
// Weights in mma-fragment order, hi/lo fp16 pairs.
// Per (matmul m, stream n): 2048 fragments * 32 lanes * 8 halves = 524288 halves.
__device__ __half g_B[3u * NS * 524288u];              // 113 MB
// h buffers in A-fragment order, hi/lo: per stream 16ks*2rt*32lane*16halves = 16384 halves.
__device__ __half g_H1[2][NS][16384];
__device__ __half g_H2[2][NS][16384];
__device__ float  g_c1[NS * HH * BB];
__device__ float  g_c2[NS * HH * BB];
__device__ float  g_Wih1p[NS * GWW];                   // permuted gate order (u*4+gt)
__device__ float  g_bg1p[NS * GWW];
__device__ float  g_bg2p[NS * GWW];
__device__ float  g_featT[FEAT * BB];                  // featT[k][b]
__device__ float  g_act[BB * HH];                      // fc1 output (post-ReLU)

// ---------------- mma wrapper ----------------
__device__ __forceinline__ void mma16816(float c[4],
                                         uint32_t a0, uint32_t a1, uint32_t a2, uint32_t a3,
                                         uint32_t b0, uint32_t b1) {
    asm volatile(
        "mma.sync.aligned.m16n8k16.row.col.f32.f16.f16.f32 "
        "{%0,%1,%2,%3}, {%4,%5,%6,%7}, {%8,%9}, {%0,%1,%2,%3};"
        : "+f"(c[0]), "+f"(c[1]), "+f"(c[2]), "+f"(c[3])
        : "r"(a0), "r"(a1), "r"(a2), "r"(a3), "r"(b0), "r"(b1));
}

// ---------------- setup kernels ----------------
// Convert big weights (Whh1, Wih2, Whh2) fp32 -> fragment-ordered hi/lo fp16.
// One thread per (m, n, frag, lane); writes 8 halves (4 hi + 4 lo).
__global__ void conv_big(const float* __restrict__ Whh1,
                         const float* __restrict__ Wih2,
                         const float* __restrict__ Whh2) {
    int idx = blockIdx.x * 256 + threadIdx.x;        // 3*36*2048*32 = 7,077,888
    if (idx >= 3 * NS * 2048 * 32) return;
    int lane = idx & 31;
    int r    = idx >> 5;
    int frag = r & 2047;          // ((bl*4+w)*8 + ct)*16 + ks
    int r2   = r >> 11;
    int n    = r2 % NS;
    int m    = r2 / NS;
    int ks   = frag & 15;
    int ct   = (frag >> 4) & 7;
    int blw  = frag >> 7;         // bl*4 + w in [0,16)
    int col  = blw * 64 + ct * 8 + (lane >> 2);   // global gate-col (permuted) [0,1024)
    int i4   = lane & 3;
    int u    = col >> 2;
    int gt   = col & 3;
    int g_orig = gt * 256 + u;    // original torch gate index
    const float* W = (m == 0) ? Whh1 : ((m == 1) ? Wih2 : Whh2);
    const float* src = W + ((size_t)n * GWW + g_orig) * HH + ks * 16;
    __half* dst = g_B + ((size_t)(m * NS + n) * 2048 + frag) * 256 + lane * 8;
    int kk0 = 2 * i4;
    int kks[4] = {kk0, kk0 + 1, kk0 + 8, kk0 + 9};
#pragma unroll
    for (int j = 0; j < 4; j++) {
        float v = src[kks[j]];
        __half hi = __float2half_rn(v);
        __half lo = __float2half_rn(v - __half2float(hi));
        dst[j]     = hi;
        dst[4 + j] = lo;
    }
}

// Permute Wih1 and fused biases into u*4+gt order.
__global__ void conv_small(const float* __restrict__ Wih1,
                           const float* __restrict__ bih1, const float* __restrict__ bhh1,
                           const float* __restrict__ bih2, const float* __restrict__ bhh2) {
    int idx = blockIdx.x * 256 + threadIdx.x;        // 36*1024
    if (idx >= NS * GWW) return;
    int n = idx >> 10;
    int col = idx & 1023;
    int u = col >> 2, gt = col & 3;
    int go = gt * 256 + u;
    int s = n * GWW + go;
    g_Wih1p[idx] = Wih1[s];
    g_bg1p[idx]  = bih1[s] + bhh1[s];
    g_bg2p[idx]  = bih2[s] + bhh2[s];
}

__global__ void init_kernel() {
    int idx = blockIdx.x * 256 + threadIdx.x;
    if (idx < 2 * NS * 16384 / 2) {                  // 589824 u32: both parities
        ((uint32_t*)g_H1)[idx] = 0u;
        ((uint32_t*)g_H2)[idx] = 0u;
    }
    if (idx < NS * HH * BB) {                        // 294912 floats
        g_c1[idx] = 0.f;
        g_c2[idx] = 0.f;
    }
}

__global__ void spec_kernel(const float* __restrict__ spec,
                            const float* __restrict__ Wspec,
                            const float* __restrict__ bspec) {
    int j = threadIdx.x;                             // [0,256)
    for (int b = 0; b < BB; b++) {
        float s = bspec[j];
#pragma unroll
        for (int i = 0; i < 6; i++) s += spec[b * 6 + i] * Wspec[i * HH + j];
        g_featT[(NS * HH + j) * BB + b] = s;
    }
}

// ---------------- GEMM core: acc += 3-term hi/lo mma over [32 x 256] x [256 x 128cols] ----------------
// Per-warp: 4 column-tiles (ct'), all 16 K-slices.
__device__ __forceinline__ void gemm3(float acc[2][4][4], const uint4* __restrict__ A,
                                      const uint4* __restrict__ Bw, int lane) {
#pragma unroll 4
    for (int ks = 0; ks < 16; ks++) {
        uint4 ahi[2], alo[2];
#pragma unroll
        for (int rt = 0; rt < 2; rt++) {
            const uint4* ap = A + ((ks * 2 + rt) * 32 + lane) * 2;
            ahi[rt] = ap[0];
            alo[rt] = ap[1];
        }
        uint4 breg[4];
#pragma unroll
        for (int ct = 0; ct < 4; ct++) breg[ct] = Bw[(ct * 16 + ks) * 32 + lane];
#pragma unroll
        for (int ct = 0; ct < 4; ct++) {
            uint4 b = breg[ct];
#pragma unroll
            for (int rt = 0; rt < 2; rt++) {
                mma16816(acc[rt][ct], ahi[rt].x, ahi[rt].y, ahi[rt].z, ahi[rt].w, b.x, b.y);  // Hhi*Whi
                mma16816(acc[rt][ct], ahi[rt].x, ahi[rt].y, ahi[rt].z, ahi[rt].w, b.z, b.w);  // Hhi*Wlo
                mma16816(acc[rt][ct], alo[rt].x, alo[rt].y, alo[rt].z, alo[rt].w, b.x, b.y);  // Hlo*Whi
            }
        }
    }
}

__device__ __forceinline__ float sigf(float v) { return 1.0f / (1.0f + expf(-v)); }

// ---------------- per-step kernel: blocks [0,144) = layer1(t), [144,288) = layer2(t-1) ----------------
// 256 threads = 8 warps; warp w8 covers 32 output cols: oldw = w8>>1 owns 64-col span,
// cthalf = w8&1 selects which half (4 of 8 ct tiles).
__global__ void __launch_bounds__(256, 2) step_kernel(int t, const float* __restrict__ x) {
    int bid = blockIdx.x;
    bool isL2 = (bid >= 144);
    int lb = isL2 ? bid - 144 : bid;
    int st = isL2 ? t - 1 : t;
    if (st < 0 || st > TST - 1) return;
    int n = lb >> 2, bl = lb & 3;
    int tid = threadIdx.x, w8 = tid >> 5, lane = tid & 31;
    int oldw = w8 >> 1, cthalf = w8 & 1;
    int rp = st & 1, wp = rp ^ 1;

    __shared__ float sg[BB * 256];

    float acc[2][4][4];
#pragma unroll
    for (int a = 0; a < 2; a++)
#pragma unroll
        for (int b = 0; b < 4; b++)
#pragma unroll
            for (int c = 0; c < 4; c++) acc[a][b][c] = 0.f;

    const uint4* Bu4 = (const uint4*)g_B;
    // warp's base fragment index within (m,n): (bl*4+oldw)*128 + cthalf*64
    size_t wfrag = (size_t)(bl * 4 + oldw) * 128 + (size_t)cthalf * 64;

    if (!isL2) {
        const uint4* Bw = Bu4 + ((size_t)(0 * NS + n) * 2048 + wfrag) * 32;
        gemm3(acc, (const uint4*)g_H1[rp][n], Bw, lane);
    } else {
        // h1(st) lives at parity (st+1)&1 == wp
        const uint4* Bw1 = Bu4 + ((size_t)(1 * NS + n) * 2048 + wfrag) * 32;
        gemm3(acc, (const uint4*)g_H1[wp][n], Bw1, lane);
        const uint4* Bw2 = Bu4 + ((size_t)(2 * NS + n) * 2048 + wfrag) * 32;
        gemm3(acc, (const uint4*)g_H2[rp][n], Bw2, lane);
    }

    // dump accumulators to shared: rows = batch, cols = block-local gate col (u_local*4+gt)
    int g8 = lane >> 2;
    int i2 = (lane & 3) * 2;
#pragma unroll
    for (int rt = 0; rt < 2; rt++)
#pragma unroll
        for (int ct = 0; ct < 4; ct++) {
            int col = w8 * 32 + ct * 8 + i2;
            int r0 = rt * 16 + g8;
            sg[r0 * 256 + col]           = acc[rt][ct][0];
            sg[r0 * 256 + col + 1]       = acc[rt][ct][1];
            sg[(r0 + 8) * 256 + col]     = acc[rt][ct][2];
            sg[(r0 + 8) * 256 + col + 1] = acc[rt][ct][3];
        }
    __syncthreads();

    float* cbuf = isL2 ? g_c2 : g_c1;
    const float* bias = isL2 ? g_bg2p : g_bg1p;
    __half* Hout = isL2 ? g_H2[wp][n] : g_H1[wp][n];

    for (int e = tid; e < BB * 64; e += 256) {
        int b  = e & 31;
        int ul = e >> 5;                 // local unit [0,64)
        int u  = bl * 64 + ul;           // unit [0,256)
        int cb = ul * 4;
        int colg = bl * 256 + cb;        // permuted col within stream
        float ip = sg[b * 256 + cb + 0] + bias[n * GWW + colg + 0];
        float fp = sg[b * 256 + cb + 1] + bias[n * GWW + colg + 1];
        float gp = sg[b * 256 + cb + 2] + bias[n * GWW + colg + 2];
        float op = sg[b * 256 + cb + 3] + bias[n * GWW + colg + 3];
        if (!isL2) {
            float xv = x[(b * TST + st) * NS + n];
            ip += xv * g_Wih1p[n * GWW + colg + 0];
            fp += xv * g_Wih1p[n * GWW + colg + 1];
            gp += xv * g_Wih1p[n * GWW + colg + 2];
            op += xv * g_Wih1p[n * GWW + colg + 3];
        }
        float iv = sigf(ip), fv = sigf(fp), gv = tanhf(gp), ov = sigf(op);
        int ci = (n * HH + u) * BB + b;
        float cv = fv * cbuf[ci] + iv * gv;
        cbuf[ci] = cv;
        float hv = ov * tanhf(cv);

        // write h into A-fragment layout (hi + lo)
        int ks = u >> 4, kk = u & 15;
        int rt = b >> 4, rl = b & 15;
        int gg = rl & 7, hirow = rl >> 3;
        int ii = (kk & 7) >> 1, p = kk & 1, hik = kk >> 3;
        int lane2 = gg * 4 + ii;
        int j = hik * 4 + hirow * 2 + p;
        __half hi = __float2half_rn(hv);
        __half lo = __float2half_rn(hv - __half2float(hi));
        __half* hp = Hout + ((ks * 2 + rt) * 32 + lane2) * 16;
        hp[j]     = hi;
        hp[j + 8] = lo;

        if (isL2) g_featT[(n * HH + u) * BB + b] = hv;
    }
}

// ---------------- classifier ----------------
__global__ void fc1_kernel(const float* __restrict__ Wp1, const float* __restrict__ bp1) {
    int tid = threadIdx.x;
    int b = tid & 31;
    int tj = tid >> 5;                      // [0,8)
    int j = blockIdx.x * 8 + tj;            // [0,256)
    const float* ft = g_featT + b;
    const float* wc = Wp1 + j;
    float a0 = 0.f, a1 = 0.f, a2 = 0.f, a3 = 0.f;
#pragma unroll 4
    for (int k = 0; k < FEAT; k += 4) {
        a0 += ft[(k + 0) * BB] * wc[(size_t)(k + 0) * HH];
        a1 += ft[(k + 1) * BB] * wc[(size_t)(k + 1) * HH];
        a2 += ft[(k + 2) * BB] * wc[(size_t)(k + 2) * HH];
        a3 += ft[(k + 3) * BB] * wc[(size_t)(k + 3) * HH];
    }
    float acc = bp1[j] + ((a0 + a1) + (a2 + a3));
    g_act[b * HH + j] = fmaxf(acc, 0.f);
}

__global__ void fc2_kernel(const float* __restrict__ Wp2, const float* __restrict__ bp2,
                           float* __restrict__ out) {
    int tid = threadIdx.x;
    if (tid >= BB * 30) return;
    int b = tid / 30, o = tid % 30;
    float acc = bp2[o];
#pragma unroll 8
    for (int k = 0; k < HH; k++) acc += g_act[b * HH + k] * Wp2[k * 30 + o];
    out[b * 30 + o] = acc;
}

// ---------------- launch ----------------
extern "C" void kernel_launch(void* const* d_in, const int* in_sizes, int n_in,
                              void* d_out, int out_size) {
    const float* x     = (const float*)d_in[0];
    const float* spec  = (const float*)d_in[1];
    const float* Wih1  = (const float*)d_in[2];
    const float* Whh1  = (const float*)d_in[3];
    const float* bih1  = (const float*)d_in[4];
    const float* bhh1  = (const float*)d_in[5];
    const float* Wih2  = (const float*)d_in[6];
    const float* Whh2  = (const float*)d_in[7];
    const float* bih2  = (const float*)d_in[8];
    const float* bhh2  = (const float*)d_in[9];
    const float* Wspec = (const float*)d_in[10];
    const float* bspec = (const float*)d_in[11];
    const float* Wp1   = (const float*)d_in[12];
    const float* bp1   = (const float*)d_in[13];
    const float* Wp2   = (const float*)d_in[14];
    const float* bp2   = (const float*)d_in[15];
    float* out = (float*)d_out;

    conv_big<<<27648, 256>>>(Whh1, Wih2, Whh2);
    conv_small<<<144, 256>>>(Wih1, bih1, bhh1, bih2, bhh2);
    init_kernel<<<2304, 256>>>();
    spec_kernel<<<1, 256>>>(spec, Wspec, bspec);

    for (int t = 0; t <= TST; t++)
        step_kernel<<<288, 256>>>(t, x);

    fc1_kernel<<<32, 256>>>(Wp1, bp1);
    fc2_kernel<<<1, 960>>>(Wp2, bp2, out);
}